// round 9
// baseline (speedup 1.0000x reference)
#include <cuda_runtime.h>
#include <math_constants.h>

#define N_SPAT 8000
#define CIN 64
#define DQK 8
#define DV 64
#define LOG2E_F 1.4426950408889634f
#define JSPLIT 4

typedef unsigned long long ull;

// ---------------- scratch (no allocations allowed) ----------------
__device__ float g_Q[2 * N_SPAT * DQK];             // [b][i][c8]
__device__ float g_K[2 * N_SPAT * DQK];             // [b][j][c8]
__device__ float g_V[2 * N_SPAT * DV];              // [b][j][c64]
__device__ float g_Opart[JSPLIT * 2 * N_SPAT * DV]; // [s][b][i][c]
__device__ float g_m[JSPLIT * 2 * N_SPAT];
__device__ float g_l[JSPLIT * 2 * N_SPAT];

// ---------------- f32x2 helpers (FFMA2 path, sm_10x) ----------------
__device__ __forceinline__ ull dup2(float x) {
    ull r;
    asm("mov.b64 %0, {%1, %1};" : "=l"(r) : "r"(__float_as_uint(x)));
    return r;
}
__device__ __forceinline__ ull pack2(float lo, float hi) {
    ull r;
    asm("mov.b64 %0, {%1, %2};" : "=l"(r) : "r"(__float_as_uint(lo)), "r"(__float_as_uint(hi)));
    return r;
}
__device__ __forceinline__ void fma2(ull& d, ull a, ull b) {
    asm("fma.rn.f32x2 %0, %1, %2, %0;" : "+l"(d) : "l"(a), "l"(b));
}
__device__ __forceinline__ ull mul2(ull a, ull b) {
    ull r;
    asm("mul.rn.f32x2 %0, %1, %2;" : "=l"(r) : "l"(a), "l"(b));
    return r;
}
__device__ __forceinline__ float lo32(ull v) { return __uint_as_float((unsigned)v); }
__device__ __forceinline__ float hi32(ull v) { return __uint_as_float((unsigned)(v >> 32)); }

// ---------------- cp.async helpers ----------------
__device__ __forceinline__ void cp_async16(void* smem, const void* gmem) {
    unsigned saddr = (unsigned)__cvta_generic_to_shared(smem);
    asm volatile("cp.async.cg.shared.global [%0], [%1], 16;\n" :: "r"(saddr), "l"(gmem));
}
__device__ __forceinline__ void cp_commit() { asm volatile("cp.async.commit_group;\n"); }
__device__ __forceinline__ void cp_wait0() { asm volatile("cp.async.wait_group 0;\n"); }

// =====================================================================
// Conv kernel: fused Q/K/V 3x3x3 SAME conv.
// Grid (5 ocGroups, 40 = z*2+yhalf, 2 b), block 200 (proven layout).
// NEW: slab stored as duplicated f32 pairs (LDS.64 broadcast operand,
// no dup-MOV per tap); weights read as LDS.128 (4 loads, not 8).
// Per tap: 1 LDS.64 + 4 LDS.128 + 8 FFMA2 -> fma-bound.
// Static smem: slab 4*3*264*8=25344 + w 4*27*16*4=6912 = 32256 B.
// =====================================================================
#define CONV_T 200
#define ICCHUNK 4
#define PSY 12
#define PSX 22
#define PS (PSY * PSX)   // 264

__global__ __launch_bounds__(CONV_T) void conv_qkv_kernel(
    const float* __restrict__ x,
    const float* __restrict__ wq, const float* __restrict__ bq,
    const float* __restrict__ wk, const float* __restrict__ bk,
    const float* __restrict__ wv, const float* __restrict__ bv)
{
    __shared__ __align__(16) ull   slab2[ICCHUNK][3][PS];
    __shared__ __align__(16) float wsm[ICCHUNK][27][16];

    const int g = blockIdx.x;
    const int z = blockIdx.y >> 1;
    const int yh = blockIdx.y & 1;
    const int b = blockIdx.z;
    const int tid = threadIdx.x;           // 0..199
    const int yl = tid / 20;               // 0..9
    const int xc = tid % 20;
    const int yg = yh * 10 + yl;
    const int ocbase = g * 16;

    ull acc[8];
#pragma unroll
    for (int o2 = 0; o2 < 8; ++o2) {
        int oc0 = ocbase + 2 * o2, oc1 = oc0 + 1;
        float b0 = (oc0 < 8) ? bq[oc0] : (oc0 < 16 ? bk[oc0 - 8] : bv[oc0 - 16]);
        float b1 = (oc1 < 8) ? bq[oc1] : (oc1 < 16 ? bk[oc1 - 8] : bv[oc1 - 16]);
        acc[o2] = pack2(b0, b1);
    }

    for (int chunk = 0; chunk < CIN / ICCHUNK; ++chunk) {
        __syncthreads();
        // fill padded duplicated slab (zero borders): rows yh*10-1 .. +10
        for (int idx = tid; idx < ICCHUNK * 3 * PS; idx += CONV_T) {
            int spl = idx % PS;
            int zz = (idx / PS) % 3;
            int ic = idx / (3 * PS);
            int yy = yh * 10 + spl / PSX - 1;
            int xx = spl % PSX - 1;
            int zg = z + zz - 1;
            float v = 0.f;
            if ((unsigned)zg < 20u && (unsigned)yy < 20u && (unsigned)xx < 20u)
                v = x[(((size_t)b * 64 + chunk * ICCHUNK + ic) * 20 + zg) * 400 + yy * 20 + xx];
            slab2[ic][zz][spl] = dup2(v);
        }
        // fill weights [ic][tap][ocl]  (oc pairs contiguous for f32x2)
        for (int idx = tid; idx < ICCHUNK * 27 * 16; idx += CONV_T) {
            int ocl = idx & 15;
            int tap = (idx >> 4) % 27;
            int ic = idx / (27 * 16);
            int oc = ocbase + ocl;
            int icg = chunk * ICCHUNK + ic;
            float w;
            if (oc < 8)       w = wq[((size_t)oc * 64 + icg) * 27 + tap];
            else if (oc < 16) w = wk[((size_t)(oc - 8) * 64 + icg) * 27 + tap];
            else              w = wv[((size_t)(oc - 16) * 64 + icg) * 27 + tap];
            wsm[ic][tap][ocl] = w;
        }
        __syncthreads();

#pragma unroll
        for (int ic = 0; ic < ICCHUNK; ++ic) {
#pragma unroll
            for (int dz = 0; dz < 3; ++dz) {
                const ull* sl = &slab2[ic][dz][yl * PSX + xc];
#pragma unroll
                for (int t9 = 0; t9 < 9; ++t9) {
                    const int dy = t9 / 3, dx = t9 % 3;
                    ull xd = sl[dy * PSX + dx];                 // LDS.64, pre-dup
                    const ulonglong2* wp = (const ulonglong2*)&wsm[ic][dz * 9 + t9][0];
                    ulonglong2 wa = wp[0], wb = wp[1];          // 4x LDS.128
                    fma2(acc[0], wa.x, xd);
                    fma2(acc[1], wa.y, xd);
                    fma2(acc[2], wb.x, xd);
                    fma2(acc[3], wb.y, xd);
                    ulonglong2 wc = wp[2], wd = wp[3];
                    fma2(acc[4], wc.x, xd);
                    fma2(acc[5], wc.y, xd);
                    fma2(acc[6], wd.x, xd);
                    fma2(acc[7], wd.y, xd);
                }
            }
        }
    }

    // vectorized stores: thread owns 16 consecutive channels for its voxel
    const int i = z * 400 + yg * 20 + xc;
    if (g == 0) {
        float4* qd = (float4*)(g_Q + ((size_t)b * N_SPAT + i) * DQK);
        qd[0] = make_float4(lo32(acc[0]), hi32(acc[0]), lo32(acc[1]), hi32(acc[1]));
        qd[1] = make_float4(lo32(acc[2]), hi32(acc[2]), lo32(acc[3]), hi32(acc[3]));
        float4* kd = (float4*)(g_K + ((size_t)b * N_SPAT + i) * DQK);
        kd[0] = make_float4(lo32(acc[4]), hi32(acc[4]), lo32(acc[5]), hi32(acc[5]));
        kd[1] = make_float4(lo32(acc[6]), hi32(acc[6]), lo32(acc[7]), hi32(acc[7]));
    } else {
        float4* vd = (float4*)(g_V + ((size_t)b * N_SPAT + i) * DV + (g - 1) * 16);
#pragma unroll
        for (int q = 0; q < 4; ++q)
            vd[q] = make_float4(lo32(acc[2 * q]), hi32(acc[2 * q]),
                                lo32(acc[2 * q + 1]), hi32(acc[2 * q + 1]));
    }
}

// =====================================================================
// Flash attention kernel (split-KV partials) — R8 structure,
// JSPLIT back to 4 (uneven split), occupancy raised to 5 CTAs/SM.
// BM=64 rows/CTA, 64 threads, 8x8 micro-tile, shuffle-P (proven).
// =====================================================================
#define BM 64
#define BN 64
#define ATT_T 64

__global__ __launch_bounds__(ATT_T, 5) void attn_kernel()
{
    __shared__ __align__(16) float sQT[DQK][BM];       // Q^T, pre-scaled log2(e)
    __shared__ __align__(16) float sKT[2][DQK][BN];    // K^T per buffer
    __shared__ __align__(16) float sV[2][BN][DV];      // V rows per buffer

    const int b = blockIdx.y;
    const int sp = blockIdx.z;
    const int i0 = blockIdx.x * BM;
    const int tid = threadIdx.x;
    const int tc = tid & 7;
    const int tr = tid >> 3;         // 0..7, rows 8tr..8tr+7
    const int lane = tid & 31;

    const int NTALL = N_SPAT / BN;   // 125
    const int t0 = (sp * NTALL) / JSPLIT;
    const int t1 = ((sp + 1) * NTALL) / JSPLIT;

    const float* Qb = g_Q + (size_t)b * N_SPAT * DQK;
    const float* Kb = g_K + (size_t)b * N_SPAT * DQK;
    const float* Vb = g_V + (size_t)b * N_SPAT * DV;

    // ---- load Q tile (row per thread), transpose, pre-scale ----
    {
        const float4* qp = (const float4*)(Qb + (size_t)(i0 + tid) * DQK);
        float4 q0 = qp[0], q1 = qp[1];
        sQT[0][tid] = q0.x * LOG2E_F; sQT[1][tid] = q0.y * LOG2E_F;
        sQT[2][tid] = q0.z * LOG2E_F; sQT[3][tid] = q0.w * LOG2E_F;
        sQT[4][tid] = q1.x * LOG2E_F; sQT[5][tid] = q1.y * LOG2E_F;
        sQT[6][tid] = q1.z * LOG2E_F; sQT[7][tid] = q1.w * LOG2E_F;
    }

    float m[8], l[8];
    ull o[8][4];
#pragma unroll
    for (int ii = 0; ii < 8; ++ii) {
        m[ii] = -CUDART_INF_F;
        l[ii] = 0.f;
#pragma unroll
        for (int c2 = 0; c2 < 4; ++c2) o[ii][c2] = 0ull;
    }

    // ---- prologue: stage tile t0 into buffer 0 ----
    {
        const float* ksrc = Kb + (size_t)t0 * BN * DQK;
        float4 k0 = ((const float4*)ksrc)[2 * tid];
        float4 k1 = ((const float4*)ksrc)[2 * tid + 1];
        const float* vsrc = Vb + (size_t)t0 * BN * DV;
#pragma unroll
        for (int q = 0; q < 16; ++q)
            cp_async16(&((float*)sV[0])[(tid + q * 64) * 4], vsrc + (size_t)(tid + q * 64) * 4);
        cp_commit();
        sKT[0][0][tid] = k0.x; sKT[0][1][tid] = k0.y;
        sKT[0][2][tid] = k0.z; sKT[0][3][tid] = k0.w;
        sKT[0][4][tid] = k1.x; sKT[0][5][tid] = k1.y;
        sKT[0][6][tid] = k1.z; sKT[0][7][tid] = k1.w;
        cp_wait0();
        __syncthreads();
    }

    for (int it = t0; it < t1; ++it) {
        const int cur = (it - t0) & 1;
        const int nxt = cur ^ 1;
        const bool pref = (it + 1 < t1);
        float4 k0r, k1r;
        if (pref) {
            const float* ksrc = Kb + (size_t)(it + 1) * BN * DQK;
            k0r = ((const float4*)ksrc)[2 * tid];
            k1r = ((const float4*)ksrc)[2 * tid + 1];
            const float* vsrc = Vb + (size_t)(it + 1) * BN * DV;
#pragma unroll
            for (int q = 0; q < 16; ++q)
                cp_async16(&((float*)sV[nxt])[(tid + q * 64) * 4], vsrc + (size_t)(tid + q * 64) * 4);
            cp_commit();
        }

        // ---- phase A: S = Q K^T (8x8 micro-tile, k=8, FFMA2 pairs) ----
        ull s2[8][4];
#pragma unroll
        for (int ii = 0; ii < 8; ++ii)
#pragma unroll
            for (int jp = 0; jp < 4; ++jp) s2[ii][jp] = 0ull;

#pragma unroll
        for (int k = 0; k < DQK; ++k) {
            float4 qa = *(const float4*)&sQT[k][8 * tr];
            float4 qb = *(const float4*)&sQT[k][8 * tr + 4];
            const ulonglong2* kp = (const ulonglong2*)&sKT[cur][k][8 * tc];
            ulonglong2 k01 = kp[0];
            ulonglong2 k23 = kp[1];
            float qv[8] = {qa.x, qa.y, qa.z, qa.w, qb.x, qb.y, qb.z, qb.w};
#pragma unroll
            for (int ii = 0; ii < 8; ++ii) {
                ull qd = dup2(qv[ii]);
                fma2(s2[ii][0], k01.x, qd);
                fma2(s2[ii][1], k01.y, qd);
                fma2(s2[ii][2], k23.x, qd);
                fma2(s2[ii][3], k23.y, qd);
            }
        }

        // ---- online softmax (base-2 domain) ----
#pragma unroll
        for (int ii = 0; ii < 8; ++ii) {
            float mx = lo32(s2[ii][0]);
            mx = fmaxf(mx, hi32(s2[ii][0]));
#pragma unroll
            for (int jp = 1; jp < 4; ++jp) {
                mx = fmaxf(mx, lo32(s2[ii][jp]));
                mx = fmaxf(mx, hi32(s2[ii][jp]));
            }
            mx = fmaxf(mx, __shfl_xor_sync(0xffffffffu, mx, 1));
            mx = fmaxf(mx, __shfl_xor_sync(0xffffffffu, mx, 2));
            mx = fmaxf(mx, __shfl_xor_sync(0xffffffffu, mx, 4));
            float mnew = fmaxf(m[ii], mx);
            float alpha = exp2f(m[ii] - mnew);
            m[ii] = mnew;
            float rs = 0.f;
#pragma unroll
            for (int jp = 0; jp < 4; ++jp) {
                float plo = exp2f(lo32(s2[ii][jp]) - mnew);
                float phi = exp2f(hi32(s2[ii][jp]) - mnew);
                s2[ii][jp] = pack2(plo, phi);   // now holds P pair
                rs += plo + phi;
            }
            rs += __shfl_xor_sync(0xffffffffu, rs, 1);
            rs += __shfl_xor_sync(0xffffffffu, rs, 2);
            rs += __shfl_xor_sync(0xffffffffu, rs, 4);
            l[ii] = l[ii] * alpha + rs;
            ull a2 = dup2(alpha);
#pragma unroll
            for (int c2 = 0; c2 < 4; ++c2) o[ii][c2] = mul2(o[ii][c2], a2);
        }

        // ---- phase C: O += P @ V  (P broadcast via shuffle, FFMA2) ----
#pragma unroll
        for (int ko = 0; ko < 8; ++ko) {
#pragma unroll
            for (int jj = 0; jj < 8; ++jj) {
                int k = ko * 8 + jj;
                const ulonglong2* vp = (const ulonglong2*)&sV[cur][k][8 * tc];
                ulonglong2 v01 = vp[0];
                ulonglong2 v23 = vp[1];
                int srcLane = (lane & 24) | ko;
#pragma unroll
                for (int ii = 0; ii < 8; ++ii) {
                    float pl = (jj & 1) ? hi32(s2[ii][jj >> 1]) : lo32(s2[ii][jj >> 1]);
                    float pv = __shfl_sync(0xffffffffu, pl, srcLane);
                    ull pd = dup2(pv);
                    fma2(o[ii][0], v01.x, pd);
                    fma2(o[ii][1], v01.y, pd);
                    fma2(o[ii][2], v23.x, pd);
                    fma2(o[ii][3], v23.y, pd);
                }
            }
        }

        if (pref) {
            sKT[nxt][0][tid] = k0r.x; sKT[nxt][1][tid] = k0r.y;
            sKT[nxt][2][tid] = k0r.z; sKT[nxt][3][tid] = k0r.w;
            sKT[nxt][4][tid] = k1r.x; sKT[nxt][5][tid] = k1r.y;
            sKT[nxt][6][tid] = k1r.z; sKT[nxt][7][tid] = k1r.w;
        }
        cp_wait0();
        __syncthreads();
    }

    // ---- epilogue: write unnormalized partials + (m,l) ----
    const size_t sb = (size_t)(sp * 2 + b);
#pragma unroll
    for (int ii = 0; ii < 8; ++ii) {
        int i = i0 + 8 * tr + ii;
        float* dst = g_Opart + (sb * N_SPAT + i) * DV + 8 * tc;
        ((float4*)dst)[0] = make_float4(lo32(o[ii][0]), hi32(o[ii][0]),
                                        lo32(o[ii][1]), hi32(o[ii][1]));
        ((float4*)dst)[1] = make_float4(lo32(o[ii][2]), hi32(o[ii][2]),
                                        lo32(o[ii][3]), hi32(o[ii][3]));
        if (tc == 0) {
            g_m[sb * N_SPAT + i] = m[ii];
            g_l[sb * N_SPAT + i] = l[ii];
        }
    }
}

// =====================================================================
// Merge kernel: combine JSPLIT partials (log-sum-exp, base-2 domain),
// transpose via smem, coalesced out[b][c][i] writes.
// =====================================================================
__global__ __launch_bounds__(256) void merge_kernel(float* __restrict__ out)
{
    __shared__ float T[DV][65];   // [c][i_local]

    const int b = blockIdx.y;
    const int i0 = blockIdx.x * 64;
    const int tid = threadIdx.x;
    const int il = tid >> 2;          // 0..63
    const int cq = tid & 3;           // channel quad group
    const int i = i0 + il;

    float mm[JSPLIT], coef[JSPLIT];
    float mstar = -CUDART_INF_F;
#pragma unroll
    for (int s = 0; s < JSPLIT; ++s) {
        mm[s] = g_m[((size_t)(s * 2 + b)) * N_SPAT + i];
        mstar = fmaxf(mstar, mm[s]);
    }
    float denom = 0.f;
#pragma unroll
    for (int s = 0; s < JSPLIT; ++s) {
        coef[s] = exp2f(mm[s] - mstar);
        denom += coef[s] * g_l[((size_t)(s * 2 + b)) * N_SPAT + i];
    }
    const float inv = 1.0f / denom;

    float acc[16];
#pragma unroll
    for (int e = 0; e < 16; ++e) acc[e] = 0.f;
#pragma unroll
    for (int s = 0; s < JSPLIT; ++s) {
        const float4* src = (const float4*)(g_Opart +
            (((size_t)(s * 2 + b)) * N_SPAT + i) * DV + cq * 16);
        float c = coef[s];
#pragma unroll
        for (int q = 0; q < 4; ++q) {
            float4 f = src[q];
            acc[4 * q + 0] = fmaf(c, f.x, acc[4 * q + 0]);
            acc[4 * q + 1] = fmaf(c, f.y, acc[4 * q + 1]);
            acc[4 * q + 2] = fmaf(c, f.z, acc[4 * q + 2]);
            acc[4 * q + 3] = fmaf(c, f.w, acc[4 * q + 3]);
        }
    }
#pragma unroll
    for (int e = 0; e < 16; ++e) T[cq * 16 + e][il] = acc[e] * inv;
    __syncthreads();

    {
        const int c = tid >> 2;
        const int ich = (tid & 3) * 16;
        float* dst = out + ((size_t)b * DV + c) * N_SPAT + i0 + ich;
#pragma unroll
        for (int q = 0; q < 4; ++q)
            ((float4*)dst)[q] = make_float4(T[c][ich + 4 * q + 0], T[c][ich + 4 * q + 1],
                                            T[c][ich + 4 * q + 2], T[c][ich + 4 * q + 3]);
    }
}

// =====================================================================
extern "C" void kernel_launch(void* const* d_in, const int* in_sizes, int n_in,
                              void* d_out, int out_size)
{
    const float* x  = (const float*)d_in[0];
    const float* wq = (const float*)d_in[1];
    const float* bq = (const float*)d_in[2];
    const float* wk = (const float*)d_in[3];
    const float* bk = (const float*)d_in[4];
    const float* wv = (const float*)d_in[5];
    const float* bv = (const float*)d_in[6];
    float* out = (float*)d_out;

    dim3 cgrid(5, 40, 2);                 // ocGroup, z*2+yhalf, batch
    conv_qkv_kernel<<<cgrid, CONV_T>>>(x, wq, bq, wk, bk, wv, bv);

    dim3 agrid(N_SPAT / BM, 2, JSPLIT);   // 125 x 2 x 4 = 1000 CTAs
    attn_kernel<<<agrid, ATT_T>>>();

    dim3 mgrid(N_SPAT / 64, 2);
    merge_kernel<<<mgrid, 256>>>(out);
}

// round 10
// speedup vs baseline: 1.9688x; 1.9688x over previous
#include <cuda_runtime.h>
#include <math_constants.h>

#define N_SPAT 8000
#define CIN 64
#define DQK 8
#define DV 64
#define LOG2E_F 1.4426950408889634f
#define JSPLIT 2

typedef unsigned long long ull;

// ---------------- scratch (no allocations allowed) ----------------
__device__ float g_Q[2 * N_SPAT * DQK];             // [b][i][c8]
__device__ float g_K[2 * N_SPAT * DQK];             // [b][j][c8]
__device__ float g_V[2 * N_SPAT * DV];              // [b][j][c64] (tf32-rounded before attn)
__device__ float g_Opart[JSPLIT * 2 * N_SPAT * DV]; // [s][b][i][c]
__device__ float g_m[JSPLIT * 2 * N_SPAT];
__device__ float g_l[JSPLIT * 2 * N_SPAT];

// ---------------- f32x2 helpers (FFMA2 path, sm_10x) ----------------
__device__ __forceinline__ ull dup2(float x) {
    ull r;
    asm("mov.b64 %0, {%1, %1};" : "=l"(r) : "r"(__float_as_uint(x)));
    return r;
}
__device__ __forceinline__ ull pack2(float lo, float hi) {
    ull r;
    asm("mov.b64 %0, {%1, %2};" : "=l"(r) : "r"(__float_as_uint(lo)), "r"(__float_as_uint(hi)));
    return r;
}
__device__ __forceinline__ void fma2(ull& d, ull a, ull b) {
    asm("fma.rn.f32x2 %0, %1, %2, %0;" : "+l"(d) : "l"(a), "l"(b));
}
__device__ __forceinline__ float lo32(ull v) { return __uint_as_float((unsigned)v); }
__device__ __forceinline__ float hi32(ull v) { return __uint_as_float((unsigned)(v >> 32)); }

// ---------------- tf32 / mma helpers ----------------
__device__ __forceinline__ float to_tf32(float x) {
    unsigned r;
    asm("cvt.rna.tf32.f32 %0, %1;" : "=r"(r) : "f"(x));
    return __uint_as_float(r);
}
__device__ __forceinline__ void mma_tf32(float* c,
    unsigned a0, unsigned a1, unsigned a2, unsigned a3,
    unsigned b0, unsigned b1)
{
    asm volatile(
        "mma.sync.aligned.m16n8k8.row.col.f32.tf32.tf32.f32 "
        "{%0,%1,%2,%3},{%4,%5,%6,%7},{%8,%9},{%0,%1,%2,%3};"
        : "+f"(c[0]), "+f"(c[1]), "+f"(c[2]), "+f"(c[3])
        : "r"(a0), "r"(a1), "r"(a2), "r"(a3), "r"(b0), "r"(b1));
}

// ---------------- cp.async helpers ----------------
__device__ __forceinline__ void cp_async16(void* smem, const void* gmem) {
    unsigned saddr = (unsigned)__cvta_generic_to_shared(smem);
    asm volatile("cp.async.cg.shared.global [%0], [%1], 16;\n" :: "r"(saddr), "l"(gmem));
}
__device__ __forceinline__ void cp_commit() { asm volatile("cp.async.commit_group;\n"); }
__device__ __forceinline__ void cp_wait0() { asm volatile("cp.async.wait_group 0;\n"); }

// =====================================================================
// Conv kernel (R5 version, proven ~268us): fused Q/K/V 3x3x3 SAME conv.
// Grid (5 ocGroups, 40 = z*2+yhalf, 2 b), block 200.
// =====================================================================
#define CONV_T 200
#define ICCHUNK 8
#define PSY 12
#define PSX 22
#define PS (PSY * PSX)   // 264

__global__ __launch_bounds__(CONV_T) void conv_qkv_kernel(
    const float* __restrict__ x,
    const float* __restrict__ wq, const float* __restrict__ bq,
    const float* __restrict__ wk, const float* __restrict__ bk,
    const float* __restrict__ wv, const float* __restrict__ bv)
{
    __shared__ __align__(16) float slab[ICCHUNK][3][PS];
    __shared__ __align__(16) float wsm[ICCHUNK][27][16];

    const int g = blockIdx.x;
    const int z = blockIdx.y >> 1;
    const int yh = blockIdx.y & 1;
    const int b = blockIdx.z;
    const int tid = threadIdx.x;           // 0..199
    const int yl = tid / 20;               // 0..9
    const int xc = tid % 20;
    const int yg = yh * 10 + yl;
    const int ocbase = g * 16;

    ull acc[8];
#pragma unroll
    for (int o2 = 0; o2 < 8; ++o2) {
        int oc0 = ocbase + 2 * o2, oc1 = oc0 + 1;
        float b0 = (oc0 < 8) ? bq[oc0] : (oc0 < 16 ? bk[oc0 - 8] : bv[oc0 - 16]);
        float b1 = (oc1 < 8) ? bq[oc1] : (oc1 < 16 ? bk[oc1 - 8] : bv[oc1 - 16]);
        acc[o2] = pack2(b0, b1);
    }

    for (int chunk = 0; chunk < CIN / ICCHUNK; ++chunk) {
        __syncthreads();
        for (int idx = tid; idx < ICCHUNK * 3 * PS; idx += CONV_T) {
            int spl = idx % PS;
            int zz = (idx / PS) % 3;
            int ic = idx / (3 * PS);
            int yy = yh * 10 + spl / PSX - 1;
            int xx = spl % PSX - 1;
            int zg = z + zz - 1;
            float v = 0.f;
            if ((unsigned)zg < 20u && (unsigned)yy < 20u && (unsigned)xx < 20u)
                v = x[(((size_t)b * 64 + chunk * ICCHUNK + ic) * 20 + zg) * 400 + yy * 20 + xx];
            slab[ic][zz][spl] = v;
        }
        for (int idx = tid; idx < ICCHUNK * 27 * 16; idx += CONV_T) {
            int ocl = idx & 15;
            int tap = (idx >> 4) % 27;
            int ic = idx / (27 * 16);
            int oc = ocbase + ocl;
            int icg = chunk * ICCHUNK + ic;
            float w;
            if (oc < 8)       w = wq[((size_t)oc * 64 + icg) * 27 + tap];
            else if (oc < 16) w = wk[((size_t)(oc - 8) * 64 + icg) * 27 + tap];
            else              w = wv[((size_t)(oc - 16) * 64 + icg) * 27 + tap];
            wsm[ic][tap][ocl] = w;
        }
        __syncthreads();

#pragma unroll 2
        for (int ic = 0; ic < ICCHUNK; ++ic) {
#pragma unroll
            for (int dz = 0; dz < 3; ++dz) {
                const float* sl = &slab[ic][dz][yl * PSX + xc];
#pragma unroll
                for (int t9 = 0; t9 < 9; ++t9) {
                    const int dy = t9 / 3, dx = t9 % 3;
                    ull xd = dup2(sl[dy * PSX + dx]);
                    const ull* wp = (const ull*)&wsm[ic][dz * 9 + t9][0];
#pragma unroll
                    for (int o2 = 0; o2 < 8; ++o2) fma2(acc[o2], wp[o2], xd);
                }
            }
        }
    }

    const int i = z * 400 + yg * 20 + xc;
    if (g == 0) {
        float4* qd = (float4*)(g_Q + ((size_t)b * N_SPAT + i) * DQK);
        qd[0] = make_float4(lo32(acc[0]), hi32(acc[0]), lo32(acc[1]), hi32(acc[1]));
        qd[1] = make_float4(lo32(acc[2]), hi32(acc[2]), lo32(acc[3]), hi32(acc[3]));
        float4* kd = (float4*)(g_K + ((size_t)b * N_SPAT + i) * DQK);
        kd[0] = make_float4(lo32(acc[4]), hi32(acc[4]), lo32(acc[5]), hi32(acc[5]));
        kd[1] = make_float4(lo32(acc[6]), hi32(acc[6]), lo32(acc[7]), hi32(acc[7]));
    } else {
        float4* vd = (float4*)(g_V + ((size_t)b * N_SPAT + i) * DV + (g - 1) * 16);
#pragma unroll
        for (int q = 0; q < 4; ++q)
            vd[q] = make_float4(lo32(acc[2 * q]), hi32(acc[2 * q]),
                                lo32(acc[2 * q + 1]), hi32(acc[2 * q + 1]));
    }
}

// =====================================================================
// Round V to tf32 in place (PV GEMM runs in tf32; Q/K stay f32).
// =====================================================================
__global__ __launch_bounds__(256) void roundv_kernel()
{
    int idx = blockIdx.x * 256 + threadIdx.x;
    if (idx < 2 * N_SPAT * DV) g_V[idx] = to_tf32(g_V[idx]);
}

// =====================================================================
// Flash attention (split-KV partials), tensor-core PV.
// BM=64 rows/CTA, 64 threads (2 warps), grid (125, 2, JSPLIT)=500 CTAs.
// Phase A: scalar f32 QK^T, 8x8 micro-tile (tr=tid>>3, tc=tid&7) - proven.
// Softmax: proven octet-shuffle path; P rounded to tf32, staged to smem
//   sP[64][68] (pad-68, warp-local -> __syncwarp only).
// Phase C: mma.sync.m16n8k8.tf32: per warp 2 m-tiles(16 rows) x 8 n-tiles
//   (c) x 8 k-slabs(j). O lives in mma accumulator fragments.
// Dyn smem (floats): sQT[8*64]@0, sKT[2*8*64]@512, sV[2*64*68]@1536,
//   sP[64*68]@10240, sAlpha[64]@14592  -> 14656 f = 58624 B. 3 CTAs/SM.
// =====================================================================
#define BM 64
#define BN 64
#define ATT_T 64
#define VPAD 68
#define ATT_SMEM_BYTES (14656 * 4)

__global__ __launch_bounds__(ATT_T) void attn_kernel()
{
    extern __shared__ __align__(16) float dyn[];
    float* sQT = dyn;              // [8][64]
    float* sKT = dyn + 512;        // [2][8][64]
    float* sV  = dyn + 1536;       // [2][64][VPAD]
    float* sP  = dyn + 10240;      // [64][VPAD]
    float* sAl = dyn + 14592;      // [64]

    const int b = blockIdx.y;
    const int sp = blockIdx.z;
    const int i0 = blockIdx.x * BM;
    const int tid = threadIdx.x;
    const int tc = tid & 7;
    const int tr = tid >> 3;          // 0..7, rows 8tr..8tr+7
    const int w = tid >> 5;           // warp 0: rows 0-31, warp 1: rows 32-63
    const int lane = tid & 31;
    const int g4 = lane >> 2;         // mma groupID 0..7
    const int q4 = lane & 3;          // mma tid-in-group

    const int NT = N_SPAT / BN;       // 125
    const int t0 = (sp * NT) / JSPLIT;
    const int t1 = ((sp + 1) * NT) / JSPLIT;

    const float* Qb = g_Q + (size_t)b * N_SPAT * DQK;
    const float* Kb = g_K + (size_t)b * N_SPAT * DQK;
    const float* Vb = g_V + (size_t)b * N_SPAT * DV;

    // ---- load Q tile (row per thread), transpose, pre-scale ----
    {
        const float4* qp = (const float4*)(Qb + (size_t)(i0 + tid) * DQK);
        float4 q0 = qp[0], q1 = qp[1];
        sQT[0 * 64 + tid] = q0.x * LOG2E_F; sQT[1 * 64 + tid] = q0.y * LOG2E_F;
        sQT[2 * 64 + tid] = q0.z * LOG2E_F; sQT[3 * 64 + tid] = q0.w * LOG2E_F;
        sQT[4 * 64 + tid] = q1.x * LOG2E_F; sQT[5 * 64 + tid] = q1.y * LOG2E_F;
        sQT[6 * 64 + tid] = q1.z * LOG2E_F; sQT[7 * 64 + tid] = q1.w * LOG2E_F;
    }

    float m[8], l[8];
    float o[2][8][4];                  // [mtile][ntile][c0..c3] mma accumulators
#pragma unroll
    for (int ii = 0; ii < 8; ++ii) { m[ii] = -CUDART_INF_F; l[ii] = 0.f; }
#pragma unroll
    for (int mt = 0; mt < 2; ++mt)
#pragma unroll
        for (int nt = 0; nt < 8; ++nt)
#pragma unroll
            for (int e = 0; e < 4; ++e) o[mt][nt][e] = 0.f;

    // ---- prologue: stage tile t0 into buffer 0 ----
    {
        const float* ksrc = Kb + (size_t)t0 * BN * DQK;
        float4 k0 = ((const float4*)ksrc)[2 * tid];
        float4 k1 = ((const float4*)ksrc)[2 * tid + 1];
        const float* vsrc = Vb + (size_t)t0 * BN * DV;
#pragma unroll
        for (int q = 0; q < 16; ++q) {
            int ch = tid + q * 64;          // 0..1023
            int row = ch >> 4, off = ch & 15;
            cp_async16(&sV[row * VPAD + off * 4], vsrc + row * 64 + off * 4);
        }
        cp_commit();
        sKT[0 * 64 + tid] = k0.x; sKT[1 * 64 + tid] = k0.y;
        sKT[2 * 64 + tid] = k0.z; sKT[3 * 64 + tid] = k0.w;
        sKT[4 * 64 + tid] = k1.x; sKT[5 * 64 + tid] = k1.y;
        sKT[6 * 64 + tid] = k1.z; sKT[7 * 64 + tid] = k1.w;
        cp_wait0();
        __syncthreads();
    }

    for (int it = t0; it < t1; ++it) {
        const int cur = (it - t0) & 1;
        const int nxt = cur ^ 1;
        const bool pref = (it + 1 < t1);
        float4 k0r, k1r;
        if (pref) {
            const float* ksrc = Kb + (size_t)(it + 1) * BN * DQK;
            k0r = ((const float4*)ksrc)[2 * tid];
            k1r = ((const float4*)ksrc)[2 * tid + 1];
            const float* vsrc = Vb + (size_t)(it + 1) * BN * DV;
#pragma unroll
            for (int q = 0; q < 16; ++q) {
                int ch = tid + q * 64;
                int row = ch >> 4, off = ch & 15;
                cp_async16(&sV[nxt * 64 * VPAD + row * VPAD + off * 4],
                           vsrc + row * 64 + off * 4);
            }
            cp_commit();
        }

        // ---- phase A: S = Q K^T (scalar f32, proven) ----
        float s[8][8];
#pragma unroll
        for (int ii = 0; ii < 8; ++ii)
#pragma unroll
            for (int jj = 0; jj < 8; ++jj) s[ii][jj] = 0.f;

#pragma unroll
        for (int k = 0; k < DQK; ++k) {
            float4 qa = *(const float4*)&sQT[k * 64 + 8 * tr];
            float4 qb = *(const float4*)&sQT[k * 64 + 8 * tr + 4];
            float4 ka = *(const float4*)&sKT[cur * 512 + k * 64 + 8 * tc];
            float4 kb = *(const float4*)&sKT[cur * 512 + k * 64 + 8 * tc + 4];
            float qv[8] = {qa.x, qa.y, qa.z, qa.w, qb.x, qb.y, qb.z, qb.w};
            float kv[8] = {ka.x, ka.y, ka.z, ka.w, kb.x, kb.y, kb.z, kb.w};
#pragma unroll
            for (int ii = 0; ii < 8; ++ii)
#pragma unroll
                for (int jj = 0; jj < 8; ++jj)
                    s[ii][jj] = fmaf(qv[ii], kv[jj], s[ii][jj]);
        }

        // ---- online softmax (base-2), publish tf32 P + alpha ----
#pragma unroll
        for (int ii = 0; ii < 8; ++ii) {
            float mx = s[ii][0];
#pragma unroll
            for (int jj = 1; jj < 8; ++jj) mx = fmaxf(mx, s[ii][jj]);
            mx = fmaxf(mx, __shfl_xor_sync(0xffffffffu, mx, 1));
            mx = fmaxf(mx, __shfl_xor_sync(0xffffffffu, mx, 2));
            mx = fmaxf(mx, __shfl_xor_sync(0xffffffffu, mx, 4));
            float mnew = fmaxf(m[ii], mx);
            float alpha = exp2f(m[ii] - mnew);
            m[ii] = mnew;
            float rs = 0.f;
            float pr[8];
#pragma unroll
            for (int jj = 0; jj < 8; ++jj) {
                float p = exp2f(s[ii][jj] - mnew);
                rs += p;
                pr[jj] = to_tf32(p);
            }
            rs += __shfl_xor_sync(0xffffffffu, rs, 1);
            rs += __shfl_xor_sync(0xffffffffu, rs, 2);
            rs += __shfl_xor_sync(0xffffffffu, rs, 4);
            l[ii] = l[ii] * alpha + rs;
            if (tc == 0) sAl[8 * tr + ii] = alpha;
            float* prow = &sP[(8 * tr + ii) * VPAD + 8 * tc];
            *(float4*)prow       = make_float4(pr[0], pr[1], pr[2], pr[3]);
            *(float4*)(prow + 4) = make_float4(pr[4], pr[5], pr[6], pr[7]);
        }
        __syncwarp();    // P/alpha rows are produced & consumed within the warp

        // ---- rescale O fragments by alpha (per fragment row) ----
        {
            float al0 = sAl[32 * w + g4];
            float ah0 = sAl[32 * w + g4 + 8];
            float al1 = sAl[32 * w + 16 + g4];
            float ah1 = sAl[32 * w + 24 + g4];
#pragma unroll
            for (int nt = 0; nt < 8; ++nt) {
                o[0][nt][0] *= al0; o[0][nt][1] *= al0;
                o[0][nt][2] *= ah0; o[0][nt][3] *= ah0;
                o[1][nt][0] *= al1; o[1][nt][1] *= al1;
                o[1][nt][2] *= ah1; o[1][nt][3] *= ah1;
            }
        }

        // ---- phase C: O += P @ V via mma.tf32 ----
        {
            const float* vb = sV + cur * 64 * VPAD;
#pragma unroll
            for (int ks = 0; ks < 8; ++ks) {
                unsigned a0[2], a1[2], a2[2], a3[2];
#pragma unroll
                for (int mt = 0; mt < 2; ++mt) {
                    int row0 = 32 * w + 16 * mt + g4;
                    a0[mt] = __float_as_uint(sP[row0 * VPAD + 8 * ks + q4]);
                    a1[mt] = __float_as_uint(sP[(row0 + 8) * VPAD + 8 * ks + q4]);
                    a2[mt] = __float_as_uint(sP[row0 * VPAD + 8 * ks + q4 + 4]);
                    a3[mt] = __float_as_uint(sP[(row0 + 8) * VPAD + 8 * ks + q4 + 4]);
                }
#pragma unroll
                for (int nt = 0; nt < 8; ++nt) {
                    unsigned b0 = __float_as_uint(vb[(8 * ks + q4) * VPAD + 8 * nt + g4]);
                    unsigned b1 = __float_as_uint(vb[(8 * ks + q4 + 4) * VPAD + 8 * nt + g4]);
                    mma_tf32(o[0][nt], a0[0], a1[0], a2[0], a3[0], b0, b1);
                    mma_tf32(o[1][nt], a0[1], a1[1], a2[1], a3[1], b0, b1);
                }
            }
        }

        if (pref) {
            float* kt = &sKT[nxt * 512];
            kt[0 * 64 + tid] = k0r.x; kt[1 * 64 + tid] = k0r.y;
            kt[2 * 64 + tid] = k0r.z; kt[3 * 64 + tid] = k0r.w;
            kt[4 * 64 + tid] = k1r.x; kt[5 * 64 + tid] = k1r.y;
            kt[6 * 64 + tid] = k1r.z; kt[7 * 64 + tid] = k1r.w;
        }
        cp_wait0();
        __syncthreads();
    }

    // ---- epilogue: partials (fragment layout) + m/l (scalar layout) ----
    const size_t sb = (size_t)(sp * 2 + b);
#pragma unroll
    for (int mt = 0; mt < 2; ++mt) {
        int R = i0 + 32 * w + 16 * mt + g4;
#pragma unroll
        for (int nt = 0; nt < 8; ++nt) {
            float2* d0 = (float2*)(g_Opart + (sb * N_SPAT + R) * DV + 8 * nt + 2 * q4);
            *d0 = make_float2(o[mt][nt][0], o[mt][nt][1]);
            float2* d1 = (float2*)(g_Opart + (sb * N_SPAT + R + 8) * DV + 8 * nt + 2 * q4);
            *d1 = make_float2(o[mt][nt][2], o[mt][nt][3]);
        }
    }
    if (tc == 0) {
#pragma unroll
        for (int ii = 0; ii < 8; ++ii) {
            int i = i0 + 8 * tr + ii;
            g_m[sb * N_SPAT + i] = m[ii];
            g_l[sb * N_SPAT + i] = l[ii];
        }
    }
}

// =====================================================================
// Merge kernel: combine JSPLIT partials (log-sum-exp, base-2 domain),
// transpose via smem, coalesced out[b][c][i] writes.
// =====================================================================
__global__ __launch_bounds__(256) void merge_kernel(float* __restrict__ out)
{
    __shared__ float T[DV][65];   // [c][i_local]

    const int b = blockIdx.y;
    const int i0 = blockIdx.x * 64;
    const int tid = threadIdx.x;
    const int il = tid >> 2;          // 0..63
    const int cq = tid & 3;           // channel quad group
    const int i = i0 + il;

    float mm[JSPLIT], coef[JSPLIT];
    float mstar = -CUDART_INF_F;
#pragma unroll
    for (int s = 0; s < JSPLIT; ++s) {
        mm[s] = g_m[((size_t)(s * 2 + b)) * N_SPAT + i];
        mstar = fmaxf(mstar, mm[s]);
    }
    float denom = 0.f;
#pragma unroll
    for (int s = 0; s < JSPLIT; ++s) {
        coef[s] = exp2f(mm[s] - mstar);
        denom += coef[s] * g_l[((size_t)(s * 2 + b)) * N_SPAT + i];
    }
    const float inv = 1.0f / denom;

    float acc[16];
#pragma unroll
    for (int e = 0; e < 16; ++e) acc[e] = 0.f;
#pragma unroll
    for (int s = 0; s < JSPLIT; ++s) {
        const float4* src = (const float4*)(g_Opart +
            (((size_t)(s * 2 + b)) * N_SPAT + i) * DV + cq * 16);
        float c = coef[s];
#pragma unroll
        for (int q = 0; q < 4; ++q) {
            float4 f = src[q];
            acc[4 * q + 0] = fmaf(c, f.x, acc[4 * q + 0]);
            acc[4 * q + 1] = fmaf(c, f.y, acc[4 * q + 1]);
            acc[4 * q + 2] = fmaf(c, f.z, acc[4 * q + 2]);
            acc[4 * q + 3] = fmaf(c, f.w, acc[4 * q + 3]);
        }
    }
#pragma unroll
    for (int e = 0; e < 16; ++e) T[cq * 16 + e][il] = acc[e] * inv;
    __syncthreads();

    {
        const int c = tid >> 2;
        const int ich = (tid & 3) * 16;
        float* dst = out + ((size_t)b * DV + c) * N_SPAT + i0 + ich;
#pragma unroll
        for (int q = 0; q < 4; ++q)
            ((float4*)dst)[q] = make_float4(T[c][ich + 4 * q + 0], T[c][ich + 4 * q + 1],
                                            T[c][ich + 4 * q + 2], T[c][ich + 4 * q + 3]);
    }
}

// =====================================================================
extern "C" void kernel_launch(void* const* d_in, const int* in_sizes, int n_in,
                              void* d_out, int out_size)
{
    const float* x  = (const float*)d_in[0];
    const float* wq = (const float*)d_in[1];
    const float* bq = (const float*)d_in[2];
    const float* wk = (const float*)d_in[3];
    const float* bk = (const float*)d_in[4];
    const float* wv = (const float*)d_in[5];
    const float* bv = (const float*)d_in[6];
    float* out = (float*)d_out;

    cudaFuncSetAttribute(attn_kernel,
                         cudaFuncAttributeMaxDynamicSharedMemorySize,
                         ATT_SMEM_BYTES);

    dim3 cgrid(5, 40, 2);                 // ocGroup, z*2+yhalf, batch
    conv_qkv_kernel<<<cgrid, CONV_T>>>(x, wq, bq, wk, bk, wv, bv);

    roundv_kernel<<<(2 * N_SPAT * DV + 255) / 256, 256>>>();

    dim3 agrid(N_SPAT / BM, 2, JSPLIT);   // 125 x 2 x 2 = 500 CTAs
    attn_kernel<<<agrid, ATT_T, ATT_SMEM_BYTES>>>();

    dim3 mgrid(N_SPAT / 64, 2);
    merge_kernel<<<mgrid, 256>>>(out);
}